// round 2
// baseline (speedup 1.0000x reference)
#include <cuda_runtime.h>
#include <math_constants.h>

#define S_LEN 1500
#define BATCHN 2
#define NH 8
#define DM 16
#define DFF 128
#define NROWS (BATCHN * S_LEN)          // 3000
#define XELEMS (NROWS * DM)             // 48000
#define QPB 42                          // queries per block (even)
#define YBLK 36                         // ceil(1500/42)

// Scratch (no allocations allowed)
__device__ float g_x[XELEMS];
__device__ float g_q[XELEMS];           // [B,H,S,2]
__device__ float g_k[XELEMS];
__device__ float g_v[XELEMS];
__device__ float g_ctx[XELEMS];

// ---------------------------------------------------------------------------
// embed + layer-0 qkv: 32 rows per 512-thread block
__global__ void __launch_bounds__(512) embed_kernel(
    const float* __restrict__ enc, const float* __restrict__ srcw,
    const float* __restrict__ srcb, const float* __restrict__ Wq,
    const float* __restrict__ Wk, const float* __restrict__ Wv)
{
    __shared__ float swq[256], swk[256], swv[256];
    int tid = threadIdx.x;
    if (tid < 256) { swq[tid] = Wq[tid]; swk[tid] = Wk[tid]; swv[tid] = Wv[tid]; }

    int r = tid >> 4, d = tid & 15;
    int grow = blockIdx.x * 32 + r;          // = b*1500 + s
    int lane = tid & 31, base = lane & 16;
    float xv = 0.f;
    if (grow < NROWS) {
        int s = grow % S_LEN;
        const float c = -0.57564627324851148f;   // -ln(10000)/16
        float dv = __expf((float)(d & ~1) * c);
        float ph = (float)s * dv;
        float pe = (d & 1) ? cosf(ph) : sinf(ph);
        xv = enc[grow] * srcw[d] + srcb[d] + pe;
        g_x[grow * DM + d] = xv;
    }
    __syncthreads();

    float xk[16];
#pragma unroll
    for (int k = 0; k < 16; k++) xk[k] = __shfl_sync(0xffffffffu, xv, base + k);
    if (grow < NROWS) {
        float q = 0.f, kk = 0.f, vv = 0.f;
#pragma unroll
        for (int m = 0; m < 16; m++) {
            q  = fmaf(xk[m], swq[m * 16 + d], q);
            kk = fmaf(xk[m], swk[m * 16 + d], kk);
            vv = fmaf(xk[m], swv[m * 16 + d], vv);
        }
        int b = grow / S_LEN, s = grow - b * S_LEN;
        int h = d >> 1, dk = d & 1;
        int o = ((b * NH + h) * S_LEN + s) * 2 + dk;
        g_q[o] = q; g_k[o] = kk; g_v[o] = vv;
    }
}

// ---------------------------------------------------------------------------
// attention: K,V interleaved float4 in SMEM, single fused pass (no max),
// 2 queries per warp per iteration, STG.128 streaming stores.
__global__ void __launch_bounds__(128) attn_kernel(float* __restrict__ attn_out)
{
    __shared__ float4 skv[S_LEN];            // (k.x,k.y,v.x,v.y)
    int bh = blockIdx.x;
    int tid = threadIdx.x;
    const float2* kp = ((const float2*)g_k) + bh * S_LEN;
    const float2* vp = ((const float2*)g_v) + bh * S_LEN;
    for (int i = tid; i < S_LEN; i += 128) {
        float2 kk = kp[i], vv = vp[i];
        skv[i] = make_float4(kk.x, kk.y, vv.x, vv.y);
    }
    __syncthreads();

    int warp = tid >> 5, lane = tid & 31;
    int q0 = blockIdx.y * QPB;
    int p0 = q0 >> 1;
    int pend = min(q0 + QPB, S_LEN) >> 1;
    int b = bh >> 3, h = bh & 7;
    const float scale = 0.70710678118654752f;

    for (int p = p0 + warp; p < pend; p += 4) {
        int qa = 2 * p, qb = 2 * p + 1;
        float2 qva = ((const float2*)g_q)[bh * S_LEN + qa];
        float2 qvb = ((const float2*)g_q)[bh * S_LEN + qb];
        qva.x *= scale; qva.y *= scale;
        qvb.x *= scale; qvb.y *= scale;

        float4 ea[12], eb[12];
        float sa = 0.f, sb = 0.f, ca0 = 0.f, ca1 = 0.f, cb0 = 0.f, cb1 = 0.f;
#pragma unroll
        for (int i = 0; i < 12; i++) {
            int i4 = lane + 32 * i;          // covers keys 4*i4 .. 4*i4+3
            if (i4 < 375) {
                float4 kv0 = skv[4 * i4 + 0];
                float4 kv1 = skv[4 * i4 + 1];
                float4 kv2 = skv[4 * i4 + 2];
                float4 kv3 = skv[4 * i4 + 3];
                float4 A, B;
                A.x = __expf(qva.x * kv0.x + qva.y * kv0.y);
                A.y = __expf(qva.x * kv1.x + qva.y * kv1.y);
                A.z = __expf(qva.x * kv2.x + qva.y * kv2.y);
                A.w = __expf(qva.x * kv3.x + qva.y * kv3.y);
                B.x = __expf(qvb.x * kv0.x + qvb.y * kv0.y);
                B.y = __expf(qvb.x * kv1.x + qvb.y * kv1.y);
                B.z = __expf(qvb.x * kv2.x + qvb.y * kv2.y);
                B.w = __expf(qvb.x * kv3.x + qvb.y * kv3.y);
                sa += (A.x + A.y) + (A.z + A.w);
                sb += (B.x + B.y) + (B.z + B.w);
                ca0 = fmaf(A.x, kv0.z, fmaf(A.y, kv1.z, fmaf(A.z, kv2.z, fmaf(A.w, kv3.z, ca0))));
                ca1 = fmaf(A.x, kv0.w, fmaf(A.y, kv1.w, fmaf(A.z, kv2.w, fmaf(A.w, kv3.w, ca1))));
                cb0 = fmaf(B.x, kv0.z, fmaf(B.y, kv1.z, fmaf(B.z, kv2.z, fmaf(B.w, kv3.z, cb0))));
                cb1 = fmaf(B.x, kv0.w, fmaf(B.y, kv1.w, fmaf(B.z, kv2.w, fmaf(B.w, kv3.w, cb1))));
                ea[i] = A; eb[i] = B;
            }
        }
#pragma unroll
        for (int o = 16; o; o >>= 1) {
            sa  += __shfl_xor_sync(0xffffffffu, sa,  o);
            sb  += __shfl_xor_sync(0xffffffffu, sb,  o);
            ca0 += __shfl_xor_sync(0xffffffffu, ca0, o);
            ca1 += __shfl_xor_sync(0xffffffffu, ca1, o);
            cb0 += __shfl_xor_sync(0xffffffffu, cb0, o);
            cb1 += __shfl_xor_sync(0xffffffffu, cb1, o);
        }
        float ra = 1.0f / sa, rb = 1.0f / sb;

        float4* rowa = (float4*)(attn_out + ((size_t)bh * S_LEN + qa) * S_LEN);
        float4* rowb = (float4*)(attn_out + ((size_t)bh * S_LEN + qb) * S_LEN);
#pragma unroll
        for (int i = 0; i < 12; i++) {
            int i4 = lane + 32 * i;
            if (i4 < 375) {
                float4 A = ea[i], B = eb[i];
                A.x *= ra; A.y *= ra; A.z *= ra; A.w *= ra;
                B.x *= rb; B.y *= rb; B.z *= rb; B.w *= rb;
                __stcs(&rowa[i4], A);
                __stcs(&rowb[i4], B);
            }
        }
        if (lane == 0) {
            int basea = (b * S_LEN + qa) * DM + h * 2;
            int baseb = (b * S_LEN + qb) * DM + h * 2;
            g_ctx[basea]     = ca0 * ra;
            g_ctx[basea + 1] = ca1 * ra;
            g_ctx[baseb]     = cb0 * rb;
            g_ctx[baseb + 1] = cb1 * rb;
        }
    }
}

// ---------------------------------------------------------------------------
// post: x=LN(ctx@Wo+x); x=LN(relu(x@W1)@W2+x); then next-layer qkv (fused).
// 512 threads = 32 rows/block, grid=94 (one wave).
__global__ void __launch_bounds__(512) post_kernel(
    const float* __restrict__ Wo, const float* __restrict__ W1,
    const float* __restrict__ W2, const float* __restrict__ Wqn,
    const float* __restrict__ Wkn, const float* __restrict__ Wvn,
    float* __restrict__ outx, int last)
{
    __shared__ float swo[256];
    __shared__ float sw1[DM * DFF];
    __shared__ float sw2[DFF * DM];
    __shared__ float swq[256], swk[256], swv[256];
    __shared__ float sh[32][DFF];

    int tid = threadIdx.x;
    if (tid < 256) swo[tid] = Wo[tid];
    for (int i = tid; i < DM * DFF; i += 512) { sw1[i] = W1[i]; sw2[i] = W2[i]; }
    if (!last && tid < 256) { swq[tid] = Wqn[tid]; swk[tid] = Wkn[tid]; swv[tid] = Wvn[tid]; }

    int r = tid >> 4, d = tid & 15;
    int grow = blockIdx.x * 32 + r;
    int lane = tid & 31, base = lane & 16;
    bool ok = grow < NROWS;
    float xv = ok ? g_x[grow * DM + d]   : 0.f;
    float cv = ok ? g_ctx[grow * DM + d] : 0.f;
    __syncthreads();

    // s1 = ctx @ Wo + x  (row exchange via shuffles inside 16-lane group)
    float s1 = xv;
#pragma unroll
    for (int k = 0; k < 16; k++) {
        float ck = __shfl_sync(0xffffffffu, cv, base + k);
        s1 = fmaf(ck, swo[k * 16 + d], s1);
    }

    // LayerNorm 1
    float mean = s1;
#pragma unroll
    for (int o = 8; o; o >>= 1) mean += __shfl_xor_sync(0xffffffffu, mean, o);
    mean *= (1.0f / 16.0f);
    float dv = s1 - mean;
    float var = dv * dv;
#pragma unroll
    for (int o = 8; o; o >>= 1) var += __shfl_xor_sync(0xffffffffu, var, o);
    var *= (1.0f / 16.0f);
    float t = dv * rsqrtf(var + 1e-5f);

    // h = relu(t @ W1): each thread does 8 of 128 hidden units
    float tk[16];
#pragma unroll
    for (int k = 0; k < 16; k++) tk[k] = __shfl_sync(0xffffffffu, t, base + k);
#pragma unroll
    for (int i = 0; i < 8; i++) {
        int j = d + 16 * i;
        float hv = 0.f;
#pragma unroll
        for (int k = 0; k < 16; k++) hv = fmaf(tk[k], sw1[k * DFF + j], hv);
        sh[r][j] = fmaxf(hv, 0.f);
    }
    __syncthreads();

    // s2 = h @ W2 + t
    float s2 = t;
#pragma unroll
    for (int j = 0; j < DFF; j++) s2 = fmaf(sh[r][j], sw2[j * 16 + d], s2);

    // LayerNorm 2
    float mean2 = s2;
#pragma unroll
    for (int o = 8; o; o >>= 1) mean2 += __shfl_xor_sync(0xffffffffu, mean2, o);
    mean2 *= (1.0f / 16.0f);
    float dv2 = s2 - mean2;
    float var2 = dv2 * dv2;
#pragma unroll
    for (int o = 8; o; o >>= 1) var2 += __shfl_xor_sync(0xffffffffu, var2, o);
    var2 *= (1.0f / 16.0f);
    float t2 = dv2 * rsqrtf(var2 + 1e-5f);

    if (last) {
        if (ok) outx[grow * DM + d] = t2;
        return;
    }

    if (ok) g_x[grow * DM + d] = t2;

    // fused next-layer qkv
    float x2k[16];
#pragma unroll
    for (int k = 0; k < 16; k++) x2k[k] = __shfl_sync(0xffffffffu, t2, base + k);
    if (ok) {
        float q = 0.f, kk = 0.f, vv = 0.f;
#pragma unroll
        for (int m = 0; m < 16; m++) {
            q  = fmaf(x2k[m], swq[m * 16 + d], q);
            kk = fmaf(x2k[m], swk[m * 16 + d], kk);
            vv = fmaf(x2k[m], swv[m * 16 + d], vv);
        }
        int b = grow / S_LEN, s = grow - b * S_LEN;
        int h = d >> 1, dk = d & 1;
        int o = ((b * NH + h) * S_LEN + s) * 2 + dk;
        g_q[o] = q; g_k[o] = kk; g_v[o] = vv;
    }
}

// ---------------------------------------------------------------------------
extern "C" void kernel_launch(void* const* d_in, const int* in_sizes, int n_in,
                              void* d_out, int out_size)
{
    const float* enc  = (const float*)d_in[0];
    const float* srcw = (const float*)d_in[1];
    const float* srcb = (const float*)d_in[2];
    const float* Wq   = (const float*)d_in[3];
    const float* Wk   = (const float*)d_in[4];
    const float* Wv   = (const float*)d_in[5];
    const float* Wo   = (const float*)d_in[6];
    const float* W1   = (const float*)d_in[7];
    const float* W2   = (const float*)d_in[8];
    float* out = (float*)d_out;

    embed_kernel<<<94, 512>>>(enc, srcw, srcb, Wq, Wk, Wv);
    for (int l = 0; l < 3; l++) {
        attn_kernel<<<dim3(BATCHN * NH, YBLK), 128>>>(
            out + XELEMS + (size_t)l * (size_t)BATCHN * NH * S_LEN * S_LEN);
        int last = (l == 2);
        post_kernel<<<94, 512>>>(Wo + l * 256, W1 + l * 2048, W2 + l * 2048,
                                 last ? Wq : Wq + (l + 1) * 256,
                                 last ? Wk : Wk + (l + 1) * 256,
                                 last ? Wv : Wv + (l + 1) * 256,
                                 out, last);
    }
}